// round 4
// baseline (speedup 1.0000x reference)
#include <cuda_runtime.h>

#define KV 16
#define DIM 15
#define NPIX (2048 * 2048)
#define TPB 256
// one thread = 2 pixels, held as a single packed f32x2 pair

typedef unsigned long long u64;

__device__ __forceinline__ u64 ffma2(u64 a, u64 b, u64 c) {
    u64 d;
    asm("fma.rn.f32x2 %0, %1, %2, %3;" : "=l"(d) : "l"(a), "l"(b), "l"(c));
    return d;
}
__device__ __forceinline__ u64 fadd2(u64 a, u64 b) {
    u64 d;
    asm("add.rn.f32x2 %0, %1, %2;" : "=l"(d) : "l"(a), "l"(b));
    return d;
}
__device__ __forceinline__ u64 pack2(float x, float y) {
    u64 p;
    asm("mov.b64 %0, {%1, %2};" : "=l"(p) : "f"(x), "f"(y));
    return p;
}
__device__ __forceinline__ void unpack2(u64 p, float& x, float& y) {
    asm("mov.b64 {%0, %1}, %2;" : "=f"(x), "=f"(y) : "l"(p));
}

// t_k = ||v_k||^2 - 2 v_k . z   (monotone in distance; argmin matches)
// dmin = sqrt(max(zz + t_min, 0))

__global__ __launch_bounds__(TPB, 3) void gum_kernel(const float* __restrict__ z,
                                                     const float* __restrict__ v,
                                                     float* __restrict__ out) {
    __shared__ __align__(16) u64 ws[DIM][KV];  // [j][k]: packed (-2v, -2v)
    __shared__ u64 bp[KV];                     // packed (||v_k||^2, ||v_k||^2)

    const int t = threadIdx.x;
    if (t < KV * DIM) {
        int k = t / DIM;
        int j = t - k * DIM;
        float w = -2.0f * v[t];
        ws[j][k] = pack2(w, w);
    }
    if (t < KV) {
        float s = 0.0f;
        #pragma unroll
        for (int j = 0; j < DIM; ++j) {
            float a = v[t * DIM + j];
            s = fmaf(a, a, s);
        }
        bp[t] = pack2(s, s);
    }
    __syncthreads();

    const size_t p = (size_t)blockIdx.x * TPB + t;  // pixel-pair index
    const u64* zp = (const u64*)z;

    // Front-batch all 15 global loads (one f32x2 pair per plane, MLP=15)
    u64 zr[DIM];
    #pragma unroll
    for (int j = 0; j < DIM; ++j)
        zr[j] = __ldcs(zp + (size_t)j * (NPIX / 2) + p);

    // 16 independent accumulator chains (depth 15 each) — no RAW stalls
    u64 acc[KV];
    #pragma unroll
    for (int k = 0; k < KV; ++k)
        acc[k] = bp[k];

    #pragma unroll
    for (int j = 0; j < DIM; ++j) {
        const u64 zj = zr[j];
        const ulonglong2* wrow = (const ulonglong2*)&ws[j][0];  // 8x LDS.128 broadcast
        #pragma unroll
        for (int m = 0; m < 8; ++m) {
            ulonglong2 w = wrow[m];
            acc[2 * m]     = ffma2(w.x, zj, acc[2 * m]);
            acc[2 * m + 1] = ffma2(w.y, zj, acc[2 * m + 1]);
        }
    }

    // ||z||^2 with two split chains
    u64 za = 0ull, zb = 0ull;
    #pragma unroll
    for (int j = 0; j < DIM; j += 2) {
        za = ffma2(zr[j], zr[j], za);
        if (j + 1 < DIM) zb = ffma2(zr[j + 1], zr[j + 1], zb);
    }
    u64 zzp = fadd2(za, zb);

    // Argmin: strict <, first-wins (matches jnp.argmin tie-breaking)
    float b0, b1;
    int i0 = 0, i1 = 0;
    unpack2(acc[0], b0, b1);
    #pragma unroll
    for (int k = 1; k < KV; ++k) {
        float t0, t1;
        unpack2(acc[k], t0, t1);
        if (t0 < b0) { b0 = t0; i0 = k; }
        if (t1 < b1) { b1 = t1; i1 = k; }
    }

    float zz0, zz1;
    unpack2(zzp, zz0, zz1);

    float2 xo = make_float2((float)i0, (float)i1);
    float2 dm = make_float2(sqrtf(fmaxf(zz0 + b0, 0.0f)),
                            sqrtf(fmaxf(zz1 + b1, 0.0f)));

    __stcs((float2*)(out + 2 * p), xo);
    __stcs((float2*)(out + (size_t)NPIX + 2 * p), dm);
}

extern "C" void kernel_launch(void* const* d_in, const int* in_sizes, int n_in,
                              void* d_out, int out_size) {
    const float* z = (const float*)d_in[0];  // (15, 2048, 2048) fp32
    const float* v = (const float*)d_in[1];  // (16, 15) fp32
    float* out = (float*)d_out;              // [X (as float) | dmin], each NPIX

    const int nblocks = NPIX / (TPB * 2);    // 8192
    gum_kernel<<<nblocks, TPB>>>(z, v, out);
}

// round 5
// speedup vs baseline: 1.6710x; 1.6710x over previous
#include <cuda_runtime.h>

#define KV 16
#define DIM 15
#define NPIX (2048 * 2048)
#define TPB 256
// one thread = 2 pixels, one packed f32x2 pair per plane

typedef unsigned long long u64;

__device__ __forceinline__ u64 ffma2(u64 a, u64 b, u64 c) {
    u64 d;
    asm("fma.rn.f32x2 %0, %1, %2, %3;" : "=l"(d) : "l"(a), "l"(b), "l"(c));
    return d;
}
__device__ __forceinline__ u64 fadd2(u64 a, u64 b) {
    u64 d;
    asm("add.rn.f32x2 %0, %1, %2;" : "=l"(d) : "l"(a), "l"(b));
    return d;
}
__device__ __forceinline__ u64 pack2(float x, float y) {
    u64 p;
    asm("mov.b64 %0, {%1, %2};" : "=l"(p) : "f"(x), "f"(y));
    return p;
}
__device__ __forceinline__ void unpack2(u64 p, float& x, float& y) {
    asm("mov.b64 {%0, %1}, %2;" : "=f"(x), "=f"(y) : "l"(p));
}

// Weight layout, per vertex k: 8 ulonglong2.
//   [k][m].x / .y = packed (-2*v[k][2m], dup) / (-2*v[k][2m+1], dup)  for m<7
//   [k][7].x      = packed pair for j=14
//   [k][7].y      = packed (||v_k||^2, ||v_k||^2)
__constant__ ulonglong2 c_wp[KV][8];
__device__ ulonglong2 g_wp[KV][8];

__global__ void prep_kernel(const float* __restrict__ v) {
    const int t = threadIdx.x;
    if (t < KV) {
        float b = 0.0f;
        #pragma unroll
        for (int j = 0; j < DIM; ++j) {
            float a = v[t * DIM + j];
            b = fmaf(a, a, b);
        }
        #pragma unroll
        for (int m = 0; m < 7; ++m) {
            float w0 = -2.0f * v[t * DIM + 2 * m];
            float w1 = -2.0f * v[t * DIM + 2 * m + 1];
            g_wp[t][m] = make_ulonglong2(pack2(w0, w0), pack2(w1, w1));
        }
        float w14 = -2.0f * v[t * DIM + 14];
        g_wp[t][7] = make_ulonglong2(pack2(w14, w14), pack2(b, b));
    }
}

// t_k = ||v_k||^2 - 2 v_k . z   (monotone in distance; argmin matches)
// dmin = sqrt(max(zz + t_min, 0))

__global__ __launch_bounds__(TPB, 4) void gum_kernel(const float* __restrict__ z,
                                                     float* __restrict__ out) {
    const int t = threadIdx.x;
    const size_t p = (size_t)blockIdx.x * TPB + t;  // pixel-pair index
    const u64* zp = (const u64*)z;

    // Front-batch all 15 global loads (MLP=15)
    u64 zr[DIM];
    #pragma unroll
    for (int j = 0; j < DIM; ++j)
        zr[j] = __ldcs(zp + (size_t)j * (NPIX / 2) + p);

    // ||z||^2: two split chains
    u64 za = 0ull, zb = 0ull;
    #pragma unroll
    for (int j = 0; j < DIM; j += 2) {
        za = ffma2(zr[j], zr[j], za);
        if (j + 1 < DIM) zb = ffma2(zr[j + 1], zr[j + 1], zb);
    }
    const u64 zzp = fadd2(za, zb);

    float b0, b1;
    int i0 = 0, i1 = 0;

    #pragma unroll
    for (int k = 0; k < KV; ++k) {
        // weights from constant bank (uniform port) — literal indices
        ulonglong2 w7 = c_wp[k][7];
        u64 la = w7.y;                    // ||v_k||^2 pair
        u64 lb = 0ull;
        la = ffma2(w7.x, zr[14], la);
        #pragma unroll
        for (int m = 0; m < 7; ++m) {
            ulonglong2 w = c_wp[k][m];
            la = ffma2(w.x, zr[2 * m], la);
            lb = ffma2(w.y, zr[2 * m + 1], lb);
        }
        u64 tk = fadd2(la, lb);
        float t0, t1;
        unpack2(tk, t0, t1);
        if (k == 0) {
            b0 = t0; b1 = t1;
        } else {
            // strict <, first-wins: matches jnp.argmin tie-breaking
            if (t0 < b0) { b0 = t0; i0 = k; }
            if (t1 < b1) { b1 = t1; i1 = k; }
        }
    }

    float zz0, zz1;
    unpack2(zzp, zz0, zz1);

    float2 xo = make_float2((float)i0, (float)i1);
    float2 dm = make_float2(sqrtf(fmaxf(zz0 + b0, 0.0f)),
                            sqrtf(fmaxf(zz1 + b1, 0.0f)));

    __stcs((float2*)(out + 2 * p), xo);
    __stcs((float2*)(out + (size_t)NPIX + 2 * p), dm);
}

extern "C" void kernel_launch(void* const* d_in, const int* in_sizes, int n_in,
                              void* d_out, int out_size) {
    const float* z = (const float*)d_in[0];  // (15, 2048, 2048) fp32
    const float* v = (const float*)d_in[1];  // (16, 15) fp32
    float* out = (float*)d_out;              // [X (as float) | dmin], each NPIX

    prep_kernel<<<1, 32>>>(v);

    void* src = nullptr;
    cudaGetSymbolAddress(&src, g_wp);
    cudaMemcpyToSymbolAsync(c_wp, src, sizeof(g_wp), 0,
                            cudaMemcpyDeviceToDevice, 0);

    const int nblocks = NPIX / (TPB * 2);    // 8192
    gum_kernel<<<nblocks, TPB>>>(z, out);
}